// round 2
// baseline (speedup 1.0000x reference)
#include <cuda_runtime.h>
#include <cstdint>

#define B   32
#define N   4096
#define H   256
#define NNZ 65536
#define NC  32               // n-chunks for the weighted-sum pass
#define ROWS_PER_CHUNK (N / NC)   // 128

__device__ float g_score[B * N];
__device__ float g_attn[B * N];
__device__ float g_r[B];
__device__ float g_partial[B * NC * H];

__device__ __forceinline__ float neg_inf() { return __int_as_float(0xff800000); }

// ---------------------------------------------------------------------------
// 1) Fill dense score buffer with -inf
// ---------------------------------------------------------------------------
__global__ void k_fill() {
    int i = blockIdx.x * blockDim.x + threadIdx.x;
    if (i < B * N) g_score[i] = neg_inf();
}

// ---------------------------------------------------------------------------
// 2) Per-batch root contribution: r[b] = dot(x[b,0,:], W[H:2H]) + bias
// ---------------------------------------------------------------------------
__global__ void k_root(const float* __restrict__ x,
                       const float* __restrict__ W,
                       const float* __restrict__ bias) {
    int b = blockIdx.x;       // 32 blocks
    int t = threadIdx.x;      // 256 threads, one per h
    float v = x[(size_t)b * N * H + t] * __ldg(&W[H + t]);
    // warp reduce
    for (int o = 16; o; o >>= 1) v += __shfl_xor_sync(0xffffffffu, v, o);
    __shared__ float sm[8];
    if ((t & 31) == 0) sm[t >> 5] = v;
    __syncthreads();
    if (t == 0) {
        float s = 0.f;
        #pragma unroll
        for (int i = 0; i < 8; i++) s += sm[i];
        g_r[b] = s + bias[0];
    }
}

// ---------------------------------------------------------------------------
// 3) Score each (batch, row) pair; scatter into dense buffer.
//    One warp per pair; 8 pairs per 256-thread block. Indices are int32.
// ---------------------------------------------------------------------------
__global__ void k_score(const float* __restrict__ x,
                        const int* __restrict__ bi,
                        const int* __restrict__ ri,
                        const float* __restrict__ W) {
    int p = blockIdx.x * 8 + (threadIdx.x >> 5);
    if (p >= NNZ) return;
    int lane = threadIdx.x & 31;
    int b = bi[p];
    int n = ri[p];
    const float4* row = (const float4*)(x + ((size_t)b * N + n) * H);
    const float4* w4  = (const float4*)W;
    float s = 0.f;
    #pragma unroll
    for (int i = 0; i < 2; i++) {
        float4 xv = row[lane + 32 * i];
        float4 wv = __ldg(&w4[lane + 32 * i]);
        s += xv.x * wv.x + xv.y * wv.y + xv.z * wv.z + xv.w * wv.w;
    }
    for (int o = 16; o; o >>= 1) s += __shfl_xor_sync(0xffffffffu, s, o);
    if (lane == 0) {
        s += g_r[b];
        // reference: attn==0 -> -inf, so a valid score of exactly 0 stays -inf
        if (s != 0.0f) g_score[b * N + n] = s;
        // duplicate (b,n) pairs write identical values: benign
    }
}

// ---------------------------------------------------------------------------
// 4) Per-batch softmax over N. 32 blocks x 1024 threads, 4 elems/thread.
// ---------------------------------------------------------------------------
__global__ void k_softmax(float* __restrict__ attn_out /* may be null */) {
    int b = blockIdx.x;
    int t = threadIdx.x;
    int lane = t & 31, wid = t >> 5;
    __shared__ float sm[32];
    __shared__ float bcast;

    float v[4];
    float m = neg_inf();
    #pragma unroll
    for (int i = 0; i < 4; i++) {
        v[i] = g_score[b * N + t + i * 1024];
        m = fmaxf(m, v[i]);
    }
    for (int o = 16; o; o >>= 1) m = fmaxf(m, __shfl_xor_sync(0xffffffffu, m, o));
    if (lane == 0) sm[wid] = m;
    __syncthreads();
    if (wid == 0) {
        float mm = sm[lane];
        for (int o = 16; o; o >>= 1) mm = fmaxf(mm, __shfl_xor_sync(0xffffffffu, mm, o));
        if (lane == 0) bcast = mm;
    }
    __syncthreads();
    float M = bcast;

    float e[4];
    float sum = 0.f;
    #pragma unroll
    for (int i = 0; i < 4; i++) {
        e[i] = (v[i] == neg_inf()) ? 0.f : __expf(v[i] - M);
        sum += e[i];
    }
    for (int o = 16; o; o >>= 1) sum += __shfl_xor_sync(0xffffffffu, sum, o);
    if (lane == 0) sm[wid] = sum;
    __syncthreads();
    if (wid == 0) {
        float ss = sm[lane];
        for (int o = 16; o; o >>= 1) ss += __shfl_xor_sync(0xffffffffu, ss, o);
        if (lane == 0) bcast = ss;
    }
    __syncthreads();
    float inv = 1.f / bcast;

    #pragma unroll
    for (int i = 0; i < 4; i++) {
        float a = e[i] * inv;
        g_attn[b * N + t + i * 1024] = a;
        if (attn_out) attn_out[b * N + t + i * 1024] = a;
    }
}

// ---------------------------------------------------------------------------
// 5) Partial weighted column sums: grid (NC, B), 256 threads = one per h.
//    Skips rows with attn == 0 (invalid positions never load x).
// ---------------------------------------------------------------------------
__global__ void k_partial(const float* __restrict__ x) {
    int chunk = blockIdx.x;
    int b = blockIdx.y;
    int h = threadIdx.x;
    __shared__ float sa[ROWS_PER_CHUNK];
    int n0 = chunk * ROWS_PER_CHUNK;
    if (h < ROWS_PER_CHUNK) sa[h] = g_attn[b * N + n0 + h];
    __syncthreads();
    float acc = 0.f;
    #pragma unroll 4
    for (int r = 0; r < ROWS_PER_CHUNK; r++) {
        float a = sa[r];
        if (a != 0.f)
            acc += a * x[((size_t)b * N + n0 + r) * H + h];
    }
    g_partial[(b * NC + chunk) * H + h] = acc;
}

// ---------------------------------------------------------------------------
// 6) Reduce partials -> out[b,h]. 8192 threads.
// ---------------------------------------------------------------------------
__global__ void k_reduce(float* __restrict__ out) {
    int i = blockIdx.x * blockDim.x + threadIdx.x;
    if (i >= B * H) return;
    int b = i / H, h = i % H;
    float s = 0.f;
    #pragma unroll
    for (int c = 0; c < NC; c++) s += g_partial[(b * NC + c) * H + h];
    out[(size_t)b * H + h] = s;
}

// ---------------------------------------------------------------------------
extern "C" void kernel_launch(void* const* d_in, const int* in_sizes, int n_in,
                              void* d_out, int out_size) {
    const float* x  = (const float*)d_in[0];
    const int*   bi = (const int*)d_in[1];
    const int*   ri = (const int*)d_in[2];
    const float* W  = (const float*)d_in[3];
    const float* bs = (const float*)d_in[4];

    float* dout = (float*)d_out;
    float* out_region  = nullptr;
    float* attn_region = nullptr;
    if (out_size >= B * H + B * N) {        // (out, attn) concatenated
        out_region  = dout;
        attn_region = dout + B * H;
    } else if (out_size == B * N) {         // attn only
        attn_region = dout;
    } else {                                // out only
        out_region = dout;
    }

    k_fill<<<(B * N + 255) / 256, 256>>>();
    k_root<<<B, H>>>(x, W, bs);
    k_score<<<NNZ / 8, 256>>>(x, bi, ri, W);
    k_softmax<<<B, 1024>>>(attn_region);
    {
        dim3 g(NC, B);
        k_partial<<<g, H>>>(x);
    }
    if (out_region)
        k_reduce<<<(B * H + 255) / 256, 256>>>(out_region);
}

// round 5
// speedup vs baseline: 1.5150x; 1.5150x over previous
#include <cuda_runtime.h>
#include <cstdint>

#define B   32
#define N   4096
#define H   256
#define NC  32
#define NNZ 65536
#define ROWS_PER_CHUNK (N / NC)   // 128

__device__ float g_score[B * N];
__device__ float g_r[B];
__device__ float g_M[B];
__device__ float g_invS[B];
__device__ float g_partial[B * NC * H];
__device__ int   g_cnt[B];

__device__ __forceinline__ float neg_inf() { return __int_as_float(0xff800000); }

// ---------------------------------------------------------------------------
// 1) init: fill score buffer with -inf, reset counters, compute per-batch
//    root term r[b] = dot(x[b,0,:], W[H:2H]) + bias
//    grid: 512 fill blocks + 32 root blocks = 544 x 256
// ---------------------------------------------------------------------------
__global__ void k_init(const float* __restrict__ x,
                       const float* __restrict__ W,
                       const float* __restrict__ bias) {
    int blk = blockIdx.x;
    int t = threadIdx.x;
    if (blk < 512) {
        g_score[blk * 256 + t] = neg_inf();
        if (blk == 0 && t < B) g_cnt[t] = 0;
        return;
    }
    int b = blk - 512;
    float v = x[(size_t)b * N * H + t] * __ldg(&W[H + t]);
    for (int o = 16; o; o >>= 1) v += __shfl_xor_sync(0xffffffffu, v, o);
    __shared__ float sm[8];
    if ((t & 31) == 0) sm[t >> 5] = v;
    __syncthreads();
    if (t == 0) {
        float s = 0.f;
        #pragma unroll
        for (int i = 0; i < 8; i++) s += sm[i];
        g_r[b] = s + bias[0];
    }
}

// ---------------------------------------------------------------------------
// 2) score each (batch,row) pair, scatter into dense buffer.
//    one warp per pair, 8 pairs per block.
// ---------------------------------------------------------------------------
__global__ void k_score(const float* __restrict__ x,
                        const int* __restrict__ bi,
                        const int* __restrict__ ri,
                        const float* __restrict__ W) {
    int p = blockIdx.x * 8 + (threadIdx.x >> 5);
    int lane = threadIdx.x & 31;
    int b = bi[p];
    int n = ri[p];
    const float4* row = (const float4*)(x + ((size_t)b * N + n) * H);
    const float4* w4  = (const float4*)W;
    float s = 0.f;
    #pragma unroll
    for (int i = 0; i < 2; i++) {
        float4 xv = row[lane + 32 * i];
        float4 wv = __ldg(&w4[lane + 32 * i]);
        s += xv.x * wv.x + xv.y * wv.y + xv.z * wv.z + xv.w * wv.w;
    }
    for (int o = 16; o; o >>= 1) s += __shfl_xor_sync(0xffffffffu, s, o);
    if (lane == 0) {
        s += g_r[b];
        // reference: attn==0 -> -inf; a valid score of exactly 0 stays -inf
        if (s != 0.0f) g_score[b * N + n] = s;
    }
}

// ---------------------------------------------------------------------------
// 3) per-batch softmax stats: M[b] = max, invS[b] = 1/sum(exp(v-M)).
//    32 blocks x 1024 threads, one float4 per thread.
// ---------------------------------------------------------------------------
__global__ void k_stats() {
    int b = blockIdx.x;
    int t = threadIdx.x;
    int lane = t & 31, wid = t >> 5;
    __shared__ float sm[32];
    __shared__ float bcast;

    float4 v = ((const float4*)g_score)[b * (N / 4) + t];
    float m = fmaxf(fmaxf(v.x, v.y), fmaxf(v.z, v.w));
    for (int o = 16; o; o >>= 1) m = fmaxf(m, __shfl_xor_sync(0xffffffffu, m, o));
    if (lane == 0) sm[wid] = m;
    __syncthreads();
    if (wid == 0) {
        float mm = sm[lane];
        for (int o = 16; o; o >>= 1) mm = fmaxf(mm, __shfl_xor_sync(0xffffffffu, mm, o));
        if (lane == 0) bcast = mm;
    }
    __syncthreads();
    float M = bcast;

    float ni = neg_inf();
    float sum = (v.x == ni ? 0.f : __expf(v.x - M))
              + (v.y == ni ? 0.f : __expf(v.y - M))
              + (v.z == ni ? 0.f : __expf(v.z - M))
              + (v.w == ni ? 0.f : __expf(v.w - M));
    for (int o = 16; o; o >>= 1) sum += __shfl_xor_sync(0xffffffffu, sum, o);
    if (lane == 0) sm[wid] = sum;
    __syncthreads();
    if (wid == 0) {
        float ss = sm[lane];
        for (int o = 16; o; o >>= 1) ss += __shfl_xor_sync(0xffffffffu, ss, o);
        if (lane == 0) { g_M[b] = M; g_invS[b] = 1.f / ss; }
    }
}

// ---------------------------------------------------------------------------
// 4) fused: attn = exp(score-M)*invS (written to attn_out), partial weighted
//    column sums, and last-block-per-batch final reduce into out.
//    grid (NC, B) x 256 threads (one per h).
// ---------------------------------------------------------------------------
__global__ void k_out(const float* __restrict__ x,
                      float* __restrict__ attn_out,
                      float* __restrict__ out) {
    int chunk = blockIdx.x;
    int b = blockIdx.y;
    int h = threadIdx.x;
    int n0 = chunk * ROWS_PER_CHUNK;
    __shared__ float sa[ROWS_PER_CHUNK];

    if (h < ROWS_PER_CHUNK) {
        float v = g_score[b * N + n0 + h];
        float a = (v == neg_inf()) ? 0.f : __expf(v - g_M[b]) * g_invS[b];
        sa[h] = a;
        if (attn_out) attn_out[b * N + n0 + h] = a;
    }
    __syncthreads();

    const float* xb = x + ((size_t)b * N + n0) * H + h;
    float acc = 0.f;
    for (int r0 = 0; r0 < ROWS_PER_CHUNK; r0 += 8) {
        float xv[8];
        #pragma unroll
        for (int j = 0; j < 8; j++)
            xv[j] = (sa[r0 + j] != 0.f) ? xb[(size_t)(r0 + j) * H] : 0.f;
        #pragma unroll
        for (int j = 0; j < 8; j++)
            acc += sa[r0 + j] * xv[j];
    }
    g_partial[(b * NC + chunk) * H + h] = acc;

    if (!out) return;
    __threadfence();
    __shared__ int is_last;
    __syncthreads();
    if (h == 0) {
        int old = atomicAdd(&g_cnt[b], 1);
        is_last = (old == NC - 1);
    }
    __syncthreads();
    if (is_last) {
        float s = 0.f;
        #pragma unroll
        for (int c = 0; c < NC; c++)
            s += g_partial[(b * NC + c) * H + h];
        out[(size_t)b * H + h] = s;
    }
}

// ---------------------------------------------------------------------------
extern "C" void kernel_launch(void* const* d_in, const int* in_sizes, int n_in,
                              void* d_out, int out_size) {
    const float* x  = (const float*)d_in[0];
    const int*   bi = (const int*)d_in[1];
    const int*   ri = (const int*)d_in[2];
    const float* W  = (const float*)d_in[3];
    const float* bs = (const float*)d_in[4];

    float* dout = (float*)d_out;
    float* out_region  = nullptr;
    float* attn_region = nullptr;
    if (out_size >= B * H + B * N) {
        out_region  = dout;
        attn_region = dout + B * H;
    } else if (out_size == B * N) {
        attn_region = dout;
    } else {
        out_region = dout;
    }

    k_init<<<544, 256>>>(x, W, bs);
    k_score<<<NNZ / 8, 256>>>(x, bi, ri, W);
    k_stats<<<B, 1024>>>();
    {
        dim3 g(NC, B);
        k_out<<<g, 256>>>(x, attn_region, out_region);
    }
}

// round 6
// speedup vs baseline: 1.7273x; 1.1402x over previous
#include <cuda_runtime.h>
#include <cstdint>

#define B   32
#define N   4096
#define H   256
#define NC  32
#define NNZ 65536
#define RPC (N / NC)          // 128 rows per chunk
#define SEGS 8                // stats segments per batch
#define SEGN (N / SEGS)       // 512

__device__ float    g_score[B * N];
__device__ unsigned g_mask[B * N / 32];   // validity bitmap
__device__ float    g_r[B];
__device__ float    g_pm[B * SEGS];       // per-segment max
__device__ float    g_ps[B * SEGS];       // per-segment sum(exp(v - m_seg))
__device__ float    g_partial[B * NC * H];
__device__ int      g_cnt[B];

__device__ __forceinline__ float neg_inf() { return __int_as_float(0xff800000); }

// ---------------------------------------------------------------------------
// 1) init: zero bitmap (16KB) + counters, compute root term
//    r[b] = dot(x[b,0,:], W[H:2H]) + bias.  grid: 16 + 32 = 48 blocks x 256.
// ---------------------------------------------------------------------------
__global__ void k_init(const float* __restrict__ x,
                       const float* __restrict__ W,
                       const float* __restrict__ bias) {
    int blk = blockIdx.x;
    int t = threadIdx.x;
    if (blk < 16) {
        g_mask[blk * 256 + t] = 0u;
        if (blk == 0 && t < B) g_cnt[t] = 0;
        return;
    }
    int b = blk - 16;
    float v = x[(size_t)b * N * H + t] * __ldg(&W[H + t]);
    for (int o = 16; o; o >>= 1) v += __shfl_xor_sync(0xffffffffu, v, o);
    __shared__ float sm[8];
    if ((t & 31) == 0) sm[t >> 5] = v;
    __syncthreads();
    if (t == 0) {
        float s = 0.f;
        #pragma unroll
        for (int i = 0; i < 8; i++) s += sm[i];
        g_r[b] = s + bias[0];
    }
}

// ---------------------------------------------------------------------------
// 2) score each (batch,row) pair; write score + set validity bit.
//    one warp per pair, 8 pairs per block.
// ---------------------------------------------------------------------------
__global__ void k_score(const float* __restrict__ x,
                        const int* __restrict__ bi,
                        const int* __restrict__ ri,
                        const float* __restrict__ W) {
    int p = blockIdx.x * 8 + (threadIdx.x >> 5);
    int lane = threadIdx.x & 31;
    int b = bi[p];
    int n = ri[p];
    const float4* row = (const float4*)(x + ((size_t)b * N + n) * H);
    const float4* w4  = (const float4*)W;
    float s = 0.f;
    #pragma unroll
    for (int i = 0; i < 2; i++) {
        float4 xv = row[lane + 32 * i];
        float4 wv = __ldg(&w4[lane + 32 * i]);
        s += xv.x * wv.x + xv.y * wv.y + xv.z * wv.z + xv.w * wv.w;
    }
    for (int o = 16; o; o >>= 1) s += __shfl_xor_sync(0xffffffffu, s, o);
    if (lane == 0) {
        s += g_r[b];
        // valid score of exactly 0 stays masked (reference attn==0 -> -inf)
        if (s != 0.0f) {
            int idx = b * N + n;
            g_score[idx] = s;
            atomicOr(&g_mask[idx >> 5], 1u << (idx & 31));
        }
    }
}

// ---------------------------------------------------------------------------
// 3) partial softmax stats: one block per 512-entry segment.
//    grid B*SEGS = 256 blocks x 128 threads (one float4 each).
// ---------------------------------------------------------------------------
__global__ void k_stats() {
    int blk = blockIdx.x;            // = b*SEGS + seg
    int b = blk >> 3, seg = blk & 7;
    int t = threadIdx.x;
    int lane = t & 31, w = t >> 5;
    int base = b * N + seg * SEGN + t * 4;

    unsigned bits = (g_mask[base >> 5] >> (base & 31)) & 0xFu;
    float4 v = *(const float4*)&g_score[base];
    float ni = neg_inf();
    float x0 = (bits & 1u) ? v.x : ni;
    float x1 = (bits & 2u) ? v.y : ni;
    float x2 = (bits & 4u) ? v.z : ni;
    float x3 = (bits & 8u) ? v.w : ni;

    float m = fmaxf(fmaxf(x0, x1), fmaxf(x2, x3));
    for (int o = 16; o; o >>= 1) m = fmaxf(m, __shfl_xor_sync(0xffffffffu, m, o));
    __shared__ float sm[4];
    if (lane == 0) sm[w] = m;
    __syncthreads();
    float M = fmaxf(fmaxf(sm[0], sm[1]), fmaxf(sm[2], sm[3]));

    float s = ((bits & 1u) ? __expf(x0 - M) : 0.f)
            + ((bits & 2u) ? __expf(x1 - M) : 0.f)
            + ((bits & 4u) ? __expf(x2 - M) : 0.f)
            + ((bits & 8u) ? __expf(x3 - M) : 0.f);
    for (int o = 16; o; o >>= 1) s += __shfl_xor_sync(0xffffffffu, s, o);
    __shared__ float ss[4];
    if (lane == 0) ss[w] = s;
    __syncthreads();
    if (t == 0) {
        g_pm[blk] = M;
        g_ps[blk] = ss[0] + ss[1] + ss[2] + ss[3];
    }
}

// ---------------------------------------------------------------------------
// 4) fused: combine stats, attn = exp(score-M)*invS (-> attn_out), compact
//    valid rows, float4 weighted sum, last-block final reduce into out.
//    grid (NC, B) x 256 threads.
// ---------------------------------------------------------------------------
__global__ void k_out(const float* __restrict__ x,
                      float* __restrict__ attn_out,
                      float* __restrict__ out) {
    int chunk = blockIdx.x;
    int b = blockIdx.y;
    int tid = threadIdx.x;
    int n0 = chunk * RPC;

    __shared__ float sM, sInv;
    __shared__ float sa_val[RPC];
    __shared__ int   sa_idx[RPC];
    __shared__ int   wtot[8], wbase[8], s_n;
    __shared__ float4 gred[3][64];

    // combine segment stats (redundant per block, reads 16 floats from L2)
    if (tid == 0) {
        float M = neg_inf();
        #pragma unroll
        for (int i = 0; i < SEGS; i++) M = fmaxf(M, g_pm[b * SEGS + i]);
        float S = 0.f;
        #pragma unroll
        for (int i = 0; i < SEGS; i++) {
            float m = g_pm[b * SEGS + i];
            if (m != neg_inf()) S += g_ps[b * SEGS + i] * __expf(m - M);
        }
        sM = M;
        sInv = 1.f / S;
    }
    __syncthreads();

    // compute attn for this chunk's 128 rows; write attn_out; compact valid
    float a = 0.f;
    if (tid < RPC) {
        int idx = b * N + n0 + tid;
        bool valid = (g_mask[idx >> 5] >> (idx & 31)) & 1u;
        if (valid) a = __expf(g_score[idx] - sM) * sInv;
        if (attn_out) attn_out[idx] = a;
    }
    int lane = tid & 31, w = tid >> 5;
    unsigned m = __ballot_sync(0xffffffffu, a != 0.f);
    if (lane == 0) wtot[w] = __popc(m);
    __syncthreads();
    if (tid == 0) {
        int s = 0;
        #pragma unroll
        for (int i = 0; i < 8; i++) { wbase[i] = s; s += wtot[i]; }
        s_n = s;
    }
    __syncthreads();
    if (a != 0.f) {
        int pos = wbase[w] + __popc(m & ((1u << lane) - 1u));
        sa_val[pos] = a;
        sa_idx[pos] = tid;
    }
    __syncthreads();
    int nv = s_n;

    // weighted sum: 4 row-groups x 64 lanes, float4 per lane
    int l = tid & 63, g = tid >> 6;
    const float4* x4 = (const float4*)(x + ((size_t)b * N + n0) * H);
    float4 acc = make_float4(0.f, 0.f, 0.f, 0.f);
    int i = g;
    for (; i + 4 < nv; i += 8) {
        float a0 = sa_val[i],     a1 = sa_val[i + 4];
        int   r0 = sa_idx[i],     r1 = sa_idx[i + 4];
        float4 v0 = x4[r0 * 64 + l];
        float4 v1 = x4[r1 * 64 + l];
        acc.x += a0 * v0.x; acc.y += a0 * v0.y; acc.z += a0 * v0.z; acc.w += a0 * v0.w;
        acc.x += a1 * v1.x; acc.y += a1 * v1.y; acc.z += a1 * v1.z; acc.w += a1 * v1.w;
    }
    for (; i < nv; i += 4) {
        float av = sa_val[i];
        float4 v0 = x4[sa_idx[i] * 64 + l];
        acc.x += av * v0.x; acc.y += av * v0.y; acc.z += av * v0.z; acc.w += av * v0.w;
    }

    if (g > 0) gred[g - 1][l] = acc;
    __syncthreads();
    if (g == 0) {
        float4 t0 = gred[0][l], t1 = gred[1][l], t2 = gred[2][l];
        acc.x += t0.x + t1.x + t2.x;
        acc.y += t0.y + t1.y + t2.y;
        acc.z += t0.z + t1.z + t2.z;
        acc.w += t0.w + t1.w + t2.w;
        ((float4*)(g_partial + (size_t)(b * NC + chunk) * H))[l] = acc;
    }

    if (!out) return;
    __threadfence();
    __shared__ int is_last;
    __syncthreads();
    if (tid == 0) {
        int old = atomicAdd(&g_cnt[b], 1);
        is_last = (old == NC - 1);
    }
    __syncthreads();
    if (is_last) {
        float s = 0.f;
        #pragma unroll
        for (int c = 0; c < NC; c++)
            s += g_partial[(size_t)(b * NC + c) * H + tid];
        out[(size_t)b * H + tid] = s;
    }
}

// ---------------------------------------------------------------------------
extern "C" void kernel_launch(void* const* d_in, const int* in_sizes, int n_in,
                              void* d_out, int out_size) {
    const float* x  = (const float*)d_in[0];
    const int*   bi = (const int*)d_in[1];
    const int*   ri = (const int*)d_in[2];
    const float* W  = (const float*)d_in[3];
    const float* bs = (const float*)d_in[4];

    float* dout = (float*)d_out;
    float* out_region  = nullptr;
    float* attn_region = nullptr;
    if (out_size >= B * H + B * N) {
        out_region  = dout;
        attn_region = dout + B * H;
    } else if (out_size == B * N) {
        attn_region = dout;
    } else {
        out_region = dout;
    }

    k_init<<<48, 256>>>(x, W, bs);
    k_score<<<NNZ / 8, 256>>>(x, bi, ri, W);
    k_stats<<<B * SEGS, 128>>>();
    {
        dim3 g(NC, B);
        k_out<<<g, 256>>>(x, attn_region, out_region);
    }
}